// round 9
// baseline (speedup 1.0000x reference)
#include <cuda_runtime.h>

// QuConv: out = Re(U X U^dagger), U = Up^{kron 6}, Up 4x4 complex from 5
// weights, X real [4,4096,4096]. Output: float32 real parts (67,108,864 el).
//
// Three passes (per batch), pipelined across two streams:
//   kJ  : ALL 6 column digits (conj(Up)), full 4096-row in 68KB smem,
//         x -> g_S (complex). FMA/issue-bound (~50us/batch).
//   kA1 : row digits 0..2 (Up), 64x64 coalesced tiles, in place on g_S.
//   kA2r: row digits 3..5 (Up), stride-64 tiles, Re-only stores to d_out.
// kJ(b+1..3) overlap the DRAM-bound kA chain via event fork/join.
// Butterflies use Up = D*G*A factorization (48 packed ops vs 64 dense),
// all math packed 2-wide with fma.rn.f32x2.

typedef unsigned long long u64;
#define NQ 4096

__device__ float  g_P[2][18];                 // [0]=Up params, [1]=conj(Up)
__device__ float2 g_S[(size_t)4 * NQ * NQ];   // 512 MB complex intermediate

// ---------------- packed f32x2 helpers ----------------
__device__ __forceinline__ u64 pk2(float a, float b){
    u64 r; asm("mov.b64 %0, {%1,%2};" : "=l"(r) : "f"(a), "f"(b)); return r;
}
__device__ __forceinline__ void upk2(u64 v, float& a, float& b){
    asm("mov.b64 {%0,%1}, %2;" : "=f"(a), "=f"(b) : "l"(v));
}
__device__ __forceinline__ u64 f2fma(u64 a, u64 b, u64 c){
    u64 d; asm("fma.rn.f32x2 %0, %1, %2, %3;" : "=l"(d) : "l"(a), "l"(b), "l"(c)); return d;
}
__device__ __forceinline__ u64 f2mul(u64 a, u64 b){
    u64 d; asm("mul.rn.f32x2 %0, %1, %2;" : "=l"(d) : "l"(a), "l"(b)); return d;
}
__device__ __forceinline__ u64 f2neg(u64 a){ return a ^ 0x8000000080000000ULL; }

struct C2 { u64 re, im; };   // pair of complex numbers, SoA across f32x2 lanes

// Factored matrix params (entries duplicated across both f32x2 lanes).
struct Mat { u64 C, SA, SAn, alr[4], ali[4], ber[4], bei[4]; };

__device__ __forceinline__ Mat load_mat(int tr){
    Mat M; const float* p = g_P[tr];
    M.C   = pk2(p[0], p[0]);
    M.SA  = pk2(p[1], p[1]);
    M.SAn = pk2(-p[1], -p[1]);
#pragma unroll
    for(int r=0;r<4;r++){
        M.alr[r] = pk2(p[2+r],  p[2+r]);
        M.ali[r] = pk2(p[6+r],  p[6+r]);
        M.ber[r] = pk2(p[10+r], p[10+r]);
        M.bei[r] = pk2(p[14+r], p[14+r]);
    }
    return M;
}

// stage DG: out_r = al_r*y_r + be_r*y_{3-r}  (full complex)
__device__ __forceinline__ void dg4(const C2* __restrict__ y, C2* __restrict__ o,
                                    const Mat& M){
    u64 ny[4];
#pragma unroll
    for(int r=0;r<4;r++) ny[r] = f2neg(y[r].im);
#pragma unroll
    for(int r=0;r<4;r++){
        int rp = 3-r;
        u64 re = f2mul(M.alr[r], y[r].re);
        re = f2fma(M.ali[r], ny[r],     re);
        re = f2fma(M.ber[r], y[rp].re,  re);
        re = f2fma(M.bei[r], ny[rp],    re);
        u64 im = f2mul(M.alr[r], y[r].im);
        im = f2fma(M.ali[r], y[r].re,   im);
        im = f2fma(M.ber[r], y[rp].im,  im);
        im = f2fma(M.bei[r], y[rp].re,  im);
        o[r].re = re; o[r].im = im;
    }
}

// stage DG, real outputs only (final digit; output is Re)
__device__ __forceinline__ void dg4_re(const C2* __restrict__ y, u64* __restrict__ o,
                                       const Mat& M){
    u64 ny[4];
#pragma unroll
    for(int r=0;r<4;r++) ny[r] = f2neg(y[r].im);
#pragma unroll
    for(int r=0;r<4;r++){
        int rp = 3-r;
        u64 re = f2mul(M.alr[r], y[r].re);
        re = f2fma(M.ali[r], ny[r],    re);
        re = f2fma(M.ber[r], y[rp].re, re);
        re = f2fma(M.bei[r], ny[rp],   re);
        o[r] = re;
    }
}

// stage A (complex input)
__device__ __forceinline__ void stA(const C2& a0, const C2& a1, const C2& a2,
                                    const C2& a3, C2* __restrict__ y, const Mat& M){
    y[0].re = f2fma(M.SAn, a2.im, f2mul(M.C, a0.re));
    y[0].im = f2fma(M.SA,  a2.re, f2mul(M.C, a0.im));
    y[2].re = f2fma(M.SAn, a0.im, f2mul(M.C, a2.re));
    y[2].im = f2fma(M.SA,  a0.re, f2mul(M.C, a2.im));
    y[1].re = f2fma(M.SAn, a3.im, f2mul(M.C, a1.re));
    y[1].im = f2fma(M.SA,  a3.re, f2mul(M.C, a1.im));
    y[3].re = f2fma(M.SAn, a1.im, f2mul(M.C, a3.re));
    y[3].im = f2fma(M.SA,  a1.re, f2mul(M.C, a3.im));
}

__device__ __forceinline__ void bfly4f(C2& a0, C2& a1, C2& a2, C2& a3, const Mat& M){
    C2 y[4], o[4];
    stA(a0,a1,a2,a3,y,M);
    dg4(y,o,M);
    a0=o[0]; a1=o[1]; a2=o[2]; a3=o[3];
}

// real-input butterfly (first digit of kJ)
__device__ __forceinline__ void bfly4fr(const u64* __restrict__ xr, C2* __restrict__ v,
                                        const Mat& M){
    C2 y[4];
    y[0].re = f2mul(M.C,  xr[0]); y[0].im = f2mul(M.SA, xr[2]);
    y[2].re = f2mul(M.C,  xr[2]); y[2].im = f2mul(M.SA, xr[0]);
    y[1].re = f2mul(M.C,  xr[1]); y[1].im = f2mul(M.SA, xr[3]);
    y[3].re = f2mul(M.C,  xr[3]); y[3].im = f2mul(M.SA, xr[1]);
    dg4(y,v,M);
}

// two digits (stride 1 then stride 4 in the 16-element register set)
__device__ __forceinline__ void digits2f(C2* __restrict__ v, const Mat& M){
#pragma unroll
    for(int g=0;g<4;g++) bfly4f(v[4*g],v[4*g+1],v[4*g+2],v[4*g+3], M);
#pragma unroll
    for(int g=0;g<4;g++) bfly4f(v[g],v[g+4],v[g+8],v[g+12], M);
}

// ---------------- K0: build factored params from weights ----------------
__global__ void k_build(const float* __restrict__ w, long long wn){
    if (threadIdx.x != 0 || blockIdx.x != 0) return;
    if (wn < 5) return;
    const float WM = 0.63245553203367586f;   // sqrt(2/5)
    float th0=w[0]*WM, th1=w[1]*WM, th2=w[2]*WM, th3=w[3]*WM, th4=w[4]*WM;
    float Cs = cosf(0.5f*(th0+th1)), Ss = sinf(0.5f*(th0+th1));
    float c2 = cosf(0.5f*th2), s2 = sinf(0.5f*th2);
    float e3 = 0.5f*th3, e4 = 0.5f*th4;
    float ddx[4], ddy[4];
    ddx[0]=cosf(e3+e4); ddy[0]=-sinf(e3+e4);
    ddx[1]=cosf(e3-e4); ddy[1]=-sinf(e3-e4);
    ddx[2]= ddx[1];     ddy[2]=-ddy[1];
    ddx[3]= ddx[0];     ddy[3]=-ddy[0];
    const float sg[4] = {1.f,-1.f,-1.f,1.f};
    g_P[0][0]=Cs; g_P[0][1]=-Ss;   // Up
    g_P[1][0]=Cs; g_P[1][1]= Ss;   // conj(Up)
    for(int r=0;r<4;r++){
        float alx = ddx[r]*c2,        aly = ddy[r]*c2;
        float bex = -sg[r]*s2*ddy[r], bey = sg[r]*s2*ddx[r];
        g_P[0][2+r]=alx;  g_P[0][6+r]=aly;  g_P[0][10+r]=bex;  g_P[0][14+r]=bey;
        g_P[1][2+r]=alx;  g_P[1][6+r]=-aly; g_P[1][10+r]=bex;  g_P[1][14+r]=-bey;
    }
}

// ---------------- kJ: ALL 6 column digits, 2 rows/CTA, per batch ---------
// smem: padded phys(j) = (j>>4)*17 + (j&15); sre/sim each 4352 u64 (68 KB).
// f32x2 lanes pack rows (R0, R0+1).
__global__ __launch_bounds__(256,2) void kJ(const float* __restrict__ x,
                                            int b, long long xlimf){
    extern __shared__ u64 sm[];
    u64* sre = sm;
    u64* sim = sm + 4352;
    const Mat M = load_mat(1);                 // conj(Up)
    int t = threadIdx.x;
    long long R0 = (long long)b*NQ + (long long)blockIdx.x*2;
    if ((R0 + 2) * 4096LL > xlimf) return;
    const float* x0 = x + R0*NQ;
    const float* x1 = x0 + NQ;
    C2 v[16];
    // phase 1: digits strides 1,4  (j = 16t + k)
    {
        u64 xr[16];
        int jb = t*16;
#pragma unroll
        for(int q=0;q<4;q++){
            float4 a  = *reinterpret_cast<const float4*>(x0 + jb + 4*q);
            float4 bb = *reinterpret_cast<const float4*>(x1 + jb + 4*q);
            xr[4*q+0]=pk2(a.x,bb.x); xr[4*q+1]=pk2(a.y,bb.y);
            xr[4*q+2]=pk2(a.z,bb.z); xr[4*q+3]=pk2(a.w,bb.w);
        }
#pragma unroll
        for(int g=0;g<4;g++) bfly4fr(xr+4*g, v+4*g, M);                 // digit 0 (real in)
#pragma unroll
        for(int g=0;g<4;g++) bfly4f(v[g],v[g+4],v[g+8],v[g+12], M);     // digit 1
#pragma unroll
        for(int k=0;k<16;k++){ int p=t*17+k; sre[p]=v[k].re; sim[p]=v[k].im; }
    }
    __syncthreads();
    // phase 2: digits strides 16,64  (j = low + 16m + 256top)
    {
        int low=t&15, top=t>>4;
        int base = 272*top + low;
#pragma unroll
        for(int m=0;m<16;m++){ int p=base+17*m; v[m].re=sre[p]; v[m].im=sim[p]; }
        digits2f(v, M);
#pragma unroll
        for(int m=0;m<16;m++){ int p=base+17*m; sre[p]=v[m].re; sim[p]=v[m].im; }
    }
    __syncthreads();
    // phase 3: digits strides 256,1024  (j = t + 256m), write complex rows
    {
        int b3 = (t>>4)*17 + (t&15);
#pragma unroll
        for(int m=0;m<16;m++){ int p=b3+272*m; v[m].re=sre[p]; v[m].im=sim[p]; }
        digits2f(v, M);
        float2* Y0 = g_S + R0*NQ;
        float2* Y1 = Y0 + NQ;
#pragma unroll
        for(int m=0;m<16;m++){
            int j = t + 256*m;
            float r0,r1,i0,i1;
            upk2(v[m].re,r0,r1); upk2(v[m].im,i0,i1);
            Y0[j]=make_float2(r0,i0);
            Y1[j]=make_float2(r1,i1);
        }
    }
}

// ---------------- kA1: row digits 0..2, 64x64 coalesced tiles ------------
__global__ __launch_bounds__(128) void kA1(int b){
    float2* __restrict__ p = g_S;
    __shared__ u64 sre[2048];
    __shared__ u64 sim[2048];
    const Mat M = load_mat(0);                 // Up
    int t = threadIdx.x;
    long long base = ((long long)(b*4096 + blockIdx.y*64))*4096LL + blockIdx.x*64;
    int jp = t & 31;
    int g  = t >> 5;
    C2 v[16];
#pragma unroll
    for(int k=0;k<16;k++){
        long long m = 16*g + k;
        float4 d4 = *reinterpret_cast<const float4*>(p + base + m*4096 + 2*jp);
        v[k].re = pk2(d4.x, d4.z);
        v[k].im = pk2(d4.y, d4.w);
    }
    digits2f(v, M);
#pragma unroll
    for(int k=0;k<16;k++){ int m=16*g+k; sre[m*32+jp]=v[k].re; sim[m*32+jp]=v[k].im; }
    __syncthreads();
    int lo0 = g*4;
#pragma unroll
    for(int q=0;q<4;q++){
        int lo = lo0 + q;
        C2 wv[4];
#pragma unroll
        for(int mm=0;mm<4;mm++){ int m=lo+16*mm; wv[mm].re=sre[m*32+jp]; wv[mm].im=sim[m*32+jp]; }
        bfly4f(wv[0],wv[1],wv[2],wv[3], M);
#pragma unroll
        for(int mm=0;mm<4;mm++){
            long long m = lo + 16*mm;
            float r0,r1,i0,i1;
            upk2(wv[mm].re,r0,r1); upk2(wv[mm].im,i0,i1);
            float4 o = make_float4(r0,i0,r1,i1);
            *reinterpret_cast<float4*>(p + base + m*4096 + 2*jp) = o;
        }
    }
}

// ---------------- kA2r: row digits 3..5, Re-only stores to out -----------
__global__ __launch_bounds__(128) void kA2r(float* __restrict__ outf,
                                            int b, long long olimf){
    constexpr long long CS = 262144;           // 64 * 4096
    const float2* __restrict__ p = g_S;
    __shared__ u64 sre[2048];
    __shared__ u64 sim[2048];
    const Mat M = load_mat(0);                 // Up
    int t = threadIdx.x;
    long long base = ((long long)(b*4096 + blockIdx.y))*4096LL + blockIdx.x*64;
    if (base + 63*CS + 64 > olimf) return;
    int jp = t & 31;
    int g  = t >> 5;
    C2 v[16];
#pragma unroll
    for(int k=0;k<16;k++){
        long long m = 16*g + k;
        float4 d4 = *reinterpret_cast<const float4*>(p + base + m*CS + 2*jp);
        v[k].re = pk2(d4.x, d4.z);
        v[k].im = pk2(d4.y, d4.w);
    }
    digits2f(v, M);
#pragma unroll
    for(int k=0;k<16;k++){ int m=16*g+k; sre[m*32+jp]=v[k].re; sim[m*32+jp]=v[k].im; }
    __syncthreads();
    int lo0 = g*4;
#pragma unroll
    for(int q=0;q<4;q++){
        int lo = lo0 + q;
        C2 wv[4];
#pragma unroll
        for(int mm=0;mm<4;mm++){ int m=lo+16*mm; wv[mm].re=sre[m*32+jp]; wv[mm].im=sim[m*32+jp]; }
        C2 y[4]; u64 re4[4];
        stA(wv[0],wv[1],wv[2],wv[3], y, M);
        dg4_re(y, re4, M);
#pragma unroll
        for(int mm=0;mm<4;mm++){
            long long m = lo + 16*mm;
            float r0, r1;
            upk2(re4[mm], r0, r1);
            *reinterpret_cast<float2*>(outf + base + m*CS + 2*jp) = make_float2(r0, r1);
        }
    }
}

// ---------------- launch: per-batch pipeline across two streams ----------
extern "C" void kernel_launch(void* const* d_in, const int* in_sizes, int n_in,
                              void* d_out, int out_size){
    // identify inputs: w = smallest, x = largest
    int xi = 0, wi = 0;
    for (int i = 1; i < n_in; i++){
        if (in_sizes[i] > in_sizes[xi]) xi = i;
        if (in_sizes[i] < in_sizes[wi]) wi = i;
    }
    if (xi == wi && n_in >= 2) wi = (xi == 0) ? 1 : 0;
    const float* x = (const float*)d_in[xi];
    const float* w = (const float*)d_in[wi];
    long long xlim = (long long)in_sizes[xi];
    long long wlim = (long long)in_sizes[wi];
    long long olim = (long long)out_size;
    float* out = (float*)d_out;

    cudaFuncSetAttribute(kJ, cudaFuncAttributeMaxDynamicSharedMemorySize, 69632);

    // One-time infra (created on the eager correctness call, before capture).
    static cudaStream_t s2 = nullptr;
    static cudaEvent_t  evJ[4] = {nullptr,nullptr,nullptr,nullptr};
    static cudaEvent_t  evEnd = nullptr;
    static bool tried = false, pipe_ok = false;
    if (!tried){
        tried = true;
        pipe_ok = (cudaStreamCreateWithFlags(&s2, cudaStreamNonBlocking) == cudaSuccess);
        for (int b = 0; b < 4 && pipe_ok; b++)
            pipe_ok = (cudaEventCreateWithFlags(&evJ[b], cudaEventDisableTiming) == cudaSuccess);
        if (pipe_ok)
            pipe_ok = (cudaEventCreateWithFlags(&evEnd, cudaEventDisableTiming) == cudaSuccess);
    }

    k_build<<<1, 32>>>(w, wlim);

    if (pipe_ok){
        for (int b = 0; b < 4; b++){
            kJ<<<2048, 256, 69632>>>(x, b, xlim);
            cudaEventRecord(evJ[b], 0);
        }
        for (int b = 0; b < 4; b++){
            cudaStreamWaitEvent(s2, evJ[b], 0);
            kA1 <<<dim3(64, 64), 128, 0, s2>>>(b);
            kA2r<<<dim3(64, 64), 128, 0, s2>>>(out, b, olim);
        }
        cudaEventRecord(evEnd, s2);
        cudaStreamWaitEvent(0, evEnd, 0);
    } else {
        for (int b = 0; b < 4; b++) kJ<<<2048, 256, 69632>>>(x, b, xlim);
        for (int b = 0; b < 4; b++){
            kA1 <<<dim3(64, 64), 128>>>(b);
            kA2r<<<dim3(64, 64), 128>>>(out, b, olim);
        }
    }
}

// round 10
// speedup vs baseline: 1.0469x; 1.0469x over previous
#include <cuda_runtime.h>

// QuConv: out = Re(U X U^dagger), U = Up^{kron 6}, Up 4x4 complex from 5
// weights, X real [4,4096,4096]. Output: float32 real parts (67,108,864 el).
//
// Three sequential passes (R8 structure — R9's stream pipeline regressed):
//   kJ  : ALL 6 column digits (conj(Up)), full 4096-row in 64KB smem,
//         x -> g_S (complex). Issue-bound; smem now XOR-swizzled
//         phys(j) = j ^ ((j>>4)&15)  -> bank-conflict-free in all 3 phases.
//   kA1 : row digits 0..2 (Up), 64x64 coalesced tiles, in place on g_S.
//   kA2r: row digits 3..5 (Up), stride-64 tiles, Re-only stores to d_out.
// Butterflies use Up = D*G*A factorization (48 packed ops vs 64 dense),
// all math packed 2-wide with fma.rn.f32x2.

typedef unsigned long long u64;
#define NQ 4096

__device__ float  g_P[2][18];                 // [0]=Up params, [1]=conj(Up)
__device__ float2 g_S[(size_t)4 * NQ * NQ];   // 512 MB complex intermediate

// ---------------- packed f32x2 helpers ----------------
__device__ __forceinline__ u64 pk2(float a, float b){
    u64 r; asm("mov.b64 %0, {%1,%2};" : "=l"(r) : "f"(a), "f"(b)); return r;
}
__device__ __forceinline__ void upk2(u64 v, float& a, float& b){
    asm("mov.b64 {%0,%1}, %2;" : "=f"(a), "=f"(b) : "l"(v));
}
__device__ __forceinline__ u64 f2fma(u64 a, u64 b, u64 c){
    u64 d; asm("fma.rn.f32x2 %0, %1, %2, %3;" : "=l"(d) : "l"(a), "l"(b), "l"(c)); return d;
}
__device__ __forceinline__ u64 f2mul(u64 a, u64 b){
    u64 d; asm("mul.rn.f32x2 %0, %1, %2;" : "=l"(d) : "l"(a), "l"(b)); return d;
}
__device__ __forceinline__ u64 f2neg(u64 a){ return a ^ 0x8000000080000000ULL; }

struct C2 { u64 re, im; };   // pair of complex numbers, SoA across f32x2 lanes

// Factored matrix params (entries duplicated across both f32x2 lanes).
struct Mat { u64 C, SA, SAn, alr[4], ali[4], ber[4], bei[4]; };

__device__ __forceinline__ Mat load_mat(int tr){
    Mat M; const float* p = g_P[tr];
    M.C   = pk2(p[0], p[0]);
    M.SA  = pk2(p[1], p[1]);
    M.SAn = pk2(-p[1], -p[1]);
#pragma unroll
    for(int r=0;r<4;r++){
        M.alr[r] = pk2(p[2+r],  p[2+r]);
        M.ali[r] = pk2(p[6+r],  p[6+r]);
        M.ber[r] = pk2(p[10+r], p[10+r]);
        M.bei[r] = pk2(p[14+r], p[14+r]);
    }
    return M;
}

// stage DG: out_r = al_r*y_r + be_r*y_{3-r}  (full complex)
__device__ __forceinline__ void dg4(const C2* __restrict__ y, C2* __restrict__ o,
                                    const Mat& M){
    u64 ny[4];
#pragma unroll
    for(int r=0;r<4;r++) ny[r] = f2neg(y[r].im);
#pragma unroll
    for(int r=0;r<4;r++){
        int rp = 3-r;
        u64 re = f2mul(M.alr[r], y[r].re);
        re = f2fma(M.ali[r], ny[r],     re);
        re = f2fma(M.ber[r], y[rp].re,  re);
        re = f2fma(M.bei[r], ny[rp],    re);
        u64 im = f2mul(M.alr[r], y[r].im);
        im = f2fma(M.ali[r], y[r].re,   im);
        im = f2fma(M.ber[r], y[rp].im,  im);
        im = f2fma(M.bei[r], y[rp].re,  im);
        o[r].re = re; o[r].im = im;
    }
}

// stage DG, real outputs only (final digit; output is Re)
__device__ __forceinline__ void dg4_re(const C2* __restrict__ y, u64* __restrict__ o,
                                       const Mat& M){
    u64 ny[4];
#pragma unroll
    for(int r=0;r<4;r++) ny[r] = f2neg(y[r].im);
#pragma unroll
    for(int r=0;r<4;r++){
        int rp = 3-r;
        u64 re = f2mul(M.alr[r], y[r].re);
        re = f2fma(M.ali[r], ny[r],    re);
        re = f2fma(M.ber[r], y[rp].re, re);
        re = f2fma(M.bei[r], ny[rp],   re);
        o[r] = re;
    }
}

// stage A (complex input)
__device__ __forceinline__ void stA(const C2& a0, const C2& a1, const C2& a2,
                                    const C2& a3, C2* __restrict__ y, const Mat& M){
    y[0].re = f2fma(M.SAn, a2.im, f2mul(M.C, a0.re));
    y[0].im = f2fma(M.SA,  a2.re, f2mul(M.C, a0.im));
    y[2].re = f2fma(M.SAn, a0.im, f2mul(M.C, a2.re));
    y[2].im = f2fma(M.SA,  a0.re, f2mul(M.C, a2.im));
    y[1].re = f2fma(M.SAn, a3.im, f2mul(M.C, a1.re));
    y[1].im = f2fma(M.SA,  a3.re, f2mul(M.C, a1.im));
    y[3].re = f2fma(M.SAn, a1.im, f2mul(M.C, a3.re));
    y[3].im = f2fma(M.SA,  a1.re, f2mul(M.C, a3.im));
}

__device__ __forceinline__ void bfly4f(C2& a0, C2& a1, C2& a2, C2& a3, const Mat& M){
    C2 y[4], o[4];
    stA(a0,a1,a2,a3,y,M);
    dg4(y,o,M);
    a0=o[0]; a1=o[1]; a2=o[2]; a3=o[3];
}

// real-input butterfly (first digit of kJ)
__device__ __forceinline__ void bfly4fr(const u64* __restrict__ xr, C2* __restrict__ v,
                                        const Mat& M){
    C2 y[4];
    y[0].re = f2mul(M.C,  xr[0]); y[0].im = f2mul(M.SA, xr[2]);
    y[2].re = f2mul(M.C,  xr[2]); y[2].im = f2mul(M.SA, xr[0]);
    y[1].re = f2mul(M.C,  xr[1]); y[1].im = f2mul(M.SA, xr[3]);
    y[3].re = f2mul(M.C,  xr[3]); y[3].im = f2mul(M.SA, xr[1]);
    dg4(y,v,M);
}

// two digits (stride 1 then stride 4 in the 16-element register set)
__device__ __forceinline__ void digits2f(C2* __restrict__ v, const Mat& M){
#pragma unroll
    for(int g=0;g<4;g++) bfly4f(v[4*g],v[4*g+1],v[4*g+2],v[4*g+3], M);
#pragma unroll
    for(int g=0;g<4;g++) bfly4f(v[g],v[g+4],v[g+8],v[g+12], M);
}

// ---------------- K0: build factored params from weights ----------------
__global__ void k_build(const float* __restrict__ w, long long wn){
    if (threadIdx.x != 0 || blockIdx.x != 0) return;
    if (wn < 5) return;
    const float WM = 0.63245553203367586f;   // sqrt(2/5)
    float th0=w[0]*WM, th1=w[1]*WM, th2=w[2]*WM, th3=w[3]*WM, th4=w[4]*WM;
    float Cs = cosf(0.5f*(th0+th1)), Ss = sinf(0.5f*(th0+th1));
    float c2 = cosf(0.5f*th2), s2 = sinf(0.5f*th2);
    float e3 = 0.5f*th3, e4 = 0.5f*th4;
    float ddx[4], ddy[4];
    ddx[0]=cosf(e3+e4); ddy[0]=-sinf(e3+e4);
    ddx[1]=cosf(e3-e4); ddy[1]=-sinf(e3-e4);
    ddx[2]= ddx[1];     ddy[2]=-ddy[1];
    ddx[3]= ddx[0];     ddy[3]=-ddy[0];
    const float sg[4] = {1.f,-1.f,-1.f,1.f};
    g_P[0][0]=Cs; g_P[0][1]=-Ss;   // Up
    g_P[1][0]=Cs; g_P[1][1]= Ss;   // conj(Up)
    for(int r=0;r<4;r++){
        float alx = ddx[r]*c2,        aly = ddy[r]*c2;
        float bex = -sg[r]*s2*ddy[r], bey = sg[r]*s2*ddx[r];
        g_P[0][2+r]=alx;  g_P[0][6+r]=aly;  g_P[0][10+r]=bex;  g_P[0][14+r]=bey;
        g_P[1][2+r]=alx;  g_P[1][6+r]=-aly; g_P[1][10+r]=bex;  g_P[1][14+r]=-bey;
    }
}

// ---------------- kJ: ALL 6 column digits, 2 rows/CTA --------------------
// smem: XOR swizzle phys(j) = j ^ ((j>>4)&15). Conflict-free (u64, half-warp
// distinct mod 16) in all three phases. sre/sim each 4096 u64 (64 KB total).
// f32x2 lanes pack rows (R0, R0+1).
__global__ __launch_bounds__(256,2) void kJ(const float* __restrict__ x,
                                            long long xlimf){
    extern __shared__ u64 sm[];
    u64* sre = sm;
    u64* sim = sm + 4096;
    const Mat M = load_mat(1);                 // conj(Up)
    int t = threadIdx.x;
    long long R0 = (long long)blockIdx.x * 2;
    if ((R0 + 2) * 4096LL > xlimf) return;
    const float* x0 = x + R0*NQ;
    const float* x1 = x0 + NQ;
    int tl = t & 15;
    C2 v[16];
    // phase 1: digits strides 1,4  (j = 16t + k); phys = 16t + (k ^ tl)
    {
        u64 xr[16];
        int jb = t*16;
#pragma unroll
        for(int q=0;q<4;q++){
            float4 a  = *reinterpret_cast<const float4*>(x0 + jb + 4*q);
            float4 bb = *reinterpret_cast<const float4*>(x1 + jb + 4*q);
            xr[4*q+0]=pk2(a.x,bb.x); xr[4*q+1]=pk2(a.y,bb.y);
            xr[4*q+2]=pk2(a.z,bb.z); xr[4*q+3]=pk2(a.w,bb.w);
        }
#pragma unroll
        for(int g=0;g<4;g++) bfly4fr(xr+4*g, v+4*g, M);                 // digit 0 (real in)
#pragma unroll
        for(int g=0;g<4;g++) bfly4f(v[g],v[g+4],v[g+8],v[g+12], M);     // digit 1
#pragma unroll
        for(int k=0;k<16;k++){ int p = jb + (k ^ tl); sre[p]=v[k].re; sim[p]=v[k].im; }
    }
    __syncthreads();
    // phase 2: digits strides 16,64  (j = low + 16m + 256top);
    // phys = (low + 256top + 16m) ^ m
    {
        int low = tl, top = t>>4;
        int base = low + 256*top;
#pragma unroll
        for(int m=0;m<16;m++){ int p=(base+16*m)^m; v[m].re=sre[p]; v[m].im=sim[p]; }
        digits2f(v, M);
#pragma unroll
        for(int m=0;m<16;m++){ int p=(base+16*m)^m; sre[p]=v[m].re; sim[p]=v[m].im; }
    }
    __syncthreads();
    // phase 3: digits strides 256,1024  (j = t + 256m); phys = (t ^ x4) + 256m
    {
        int b3 = t ^ ((t>>4)&15);
#pragma unroll
        for(int m=0;m<16;m++){ int p=b3+256*m; v[m].re=sre[p]; v[m].im=sim[p]; }
        digits2f(v, M);
        float2* Y0 = g_S + R0*NQ;
        float2* Y1 = Y0 + NQ;
#pragma unroll
        for(int m=0;m<16;m++){
            int j = t + 256*m;
            float r0,r1,i0,i1;
            upk2(v[m].re,r0,r1); upk2(v[m].im,i0,i1);
            Y0[j]=make_float2(r0,i0);
            Y1[j]=make_float2(r1,i1);
        }
    }
}

// ---------------- kA1: row digits 0..2, 64x64 coalesced tiles ------------
__global__ __launch_bounds__(128) void kA1(){
    float2* __restrict__ p = g_S;
    __shared__ u64 sre[2048];
    __shared__ u64 sim[2048];
    const Mat M = load_mat(0);                 // Up
    int t = threadIdx.x;
    long long base = ((long long)(blockIdx.z*4096 + blockIdx.y*64))*4096LL + blockIdx.x*64;
    int jp = t & 31;
    int g  = t >> 5;
    C2 v[16];
#pragma unroll
    for(int k=0;k<16;k++){
        long long m = 16*g + k;
        float4 d4 = *reinterpret_cast<const float4*>(p + base + m*4096 + 2*jp);
        v[k].re = pk2(d4.x, d4.z);
        v[k].im = pk2(d4.y, d4.w);
    }
    digits2f(v, M);
#pragma unroll
    for(int k=0;k<16;k++){ int m=16*g+k; sre[m*32+jp]=v[k].re; sim[m*32+jp]=v[k].im; }
    __syncthreads();
    int lo0 = g*4;
#pragma unroll
    for(int q=0;q<4;q++){
        int lo = lo0 + q;
        C2 wv[4];
#pragma unroll
        for(int mm=0;mm<4;mm++){ int m=lo+16*mm; wv[mm].re=sre[m*32+jp]; wv[mm].im=sim[m*32+jp]; }
        bfly4f(wv[0],wv[1],wv[2],wv[3], M);
#pragma unroll
        for(int mm=0;mm<4;mm++){
            long long m = lo + 16*mm;
            float r0,r1,i0,i1;
            upk2(wv[mm].re,r0,r1); upk2(wv[mm].im,i0,i1);
            float4 o = make_float4(r0,i0,r1,i1);
            *reinterpret_cast<float4*>(p + base + m*4096 + 2*jp) = o;
        }
    }
}

// ---------------- kA2r: row digits 3..5, Re-only stores to out -----------
__global__ __launch_bounds__(128) void kA2r(float* __restrict__ outf,
                                            long long olimf){
    constexpr long long CS = 262144;           // 64 * 4096
    const float2* __restrict__ p = g_S;
    __shared__ u64 sre[2048];
    __shared__ u64 sim[2048];
    const Mat M = load_mat(0);                 // Up
    int t = threadIdx.x;
    long long base = ((long long)(blockIdx.z*4096 + blockIdx.y))*4096LL + blockIdx.x*64;
    if (base + 63*CS + 64 > olimf) return;
    int jp = t & 31;
    int g  = t >> 5;
    C2 v[16];
#pragma unroll
    for(int k=0;k<16;k++){
        long long m = 16*g + k;
        float4 d4 = *reinterpret_cast<const float4*>(p + base + m*CS + 2*jp);
        v[k].re = pk2(d4.x, d4.z);
        v[k].im = pk2(d4.y, d4.w);
    }
    digits2f(v, M);
#pragma unroll
    for(int k=0;k<16;k++){ int m=16*g+k; sre[m*32+jp]=v[k].re; sim[m*32+jp]=v[k].im; }
    __syncthreads();
    int lo0 = g*4;
#pragma unroll
    for(int q=0;q<4;q++){
        int lo = lo0 + q;
        C2 wv[4];
#pragma unroll
        for(int mm=0;mm<4;mm++){ int m=lo+16*mm; wv[mm].re=sre[m*32+jp]; wv[mm].im=sim[m*32+jp]; }
        C2 y[4]; u64 re4[4];
        stA(wv[0],wv[1],wv[2],wv[3], y, M);
        dg4_re(y, re4, M);
#pragma unroll
        for(int mm=0;mm<4;mm++){
            long long m = lo + 16*mm;
            float r0, r1;
            upk2(re4[mm], r0, r1);
            *reinterpret_cast<float2*>(outf + base + m*CS + 2*jp) = make_float2(r0, r1);
        }
    }
}

// ---------------- launch (sequential, R8 structure) ----------------------
extern "C" void kernel_launch(void* const* d_in, const int* in_sizes, int n_in,
                              void* d_out, int out_size){
    // identify inputs: w = smallest, x = largest
    int xi = 0, wi = 0;
    for (int i = 1; i < n_in; i++){
        if (in_sizes[i] > in_sizes[xi]) xi = i;
        if (in_sizes[i] < in_sizes[wi]) wi = i;
    }
    if (xi == wi && n_in >= 2) wi = (xi == 0) ? 1 : 0;
    const float* x = (const float*)d_in[xi];
    const float* w = (const float*)d_in[wi];
    long long xlim = (long long)in_sizes[xi];
    long long wlim = (long long)in_sizes[wi];
    long long olim = (long long)out_size;

    cudaFuncSetAttribute(kJ, cudaFuncAttributeMaxDynamicSharedMemorySize, 65536);

    k_build<<<1, 32>>>(w, wlim);
    kJ<<<8192, 256, 65536>>>(x, xlim);                    // all 6 column digits
    kA1<<<dim3(64, 64, 4), 128>>>();                      // row digits 0..2
    kA2r<<<dim3(64, 64, 4), 128>>>((float*)d_out, olim);  // row digits 3..5 -> Re
}

// round 11
// speedup vs baseline: 1.5147x; 1.4468x over previous
#include <cuda_runtime.h>
#include <cuda_fp16.h>

// QuConv: out = Re(U X U^dagger), U = Up^{kron 6}, Up 4x4 complex from 5
// weights, X real [4,4096,4096]. Output: float32 real parts (67,108,864 el).
//
// Three sequential passes; the complex intermediate is stored as FP16
// (half2(re,im) per element, 268 MB) — rel_err budget is 1e-3 and the fp32
// pipeline sits at 5.7e-7, so two fp16 quantizations (~3-6e-4 total) fit.
//   kJ  : ALL 6 column digits (conj(Up)), full 4096-row in 64KB smem,
//         x(fp32) -> g_S(fp16 complex). Issue-bound.
//   kA1 : row digits 0..2 (Up), 64x64 coalesced tiles, in place on g_S.
//   kA2r: row digits 3..5 (Up), stride-64 tiles, Re-only fp32 stores to d_out.
// Butterflies use Up = D*G*A factorization (48 packed ops vs 64 dense),
// all math packed 2-wide with fma.rn.f32x2 (compute stays fp32).

typedef unsigned long long u64;
typedef unsigned int u32;
#define NQ 4096

__device__ float   g_P[2][18];                 // [0]=Up params, [1]=conj(Up)
__device__ __half2 g_S[(size_t)4 * NQ * NQ];   // 268 MB fp16 complex intermediate

// ---------------- packed f32x2 helpers ----------------
__device__ __forceinline__ u64 pk2(float a, float b){
    u64 r; asm("mov.b64 %0, {%1,%2};" : "=l"(r) : "f"(a), "f"(b)); return r;
}
__device__ __forceinline__ void upk2(u64 v, float& a, float& b){
    asm("mov.b64 {%0,%1}, %2;" : "=f"(a), "=f"(b) : "l"(v));
}
__device__ __forceinline__ u64 f2fma(u64 a, u64 b, u64 c){
    u64 d; asm("fma.rn.f32x2 %0, %1, %2, %3;" : "=l"(d) : "l"(a), "l"(b), "l"(c)); return d;
}
__device__ __forceinline__ u64 f2mul(u64 a, u64 b){
    u64 d; asm("mul.rn.f32x2 %0, %1, %2;" : "=l"(d) : "l"(a), "l"(b)); return d;
}
__device__ __forceinline__ u64 f2neg(u64 a){ return a ^ 0x8000000080000000ULL; }

struct C2 { u64 re, im; };   // pair of complex numbers, SoA across f32x2 lanes

// fp16 <-> packed-pair conversion (2 complex: columns c0, c1)
__device__ __forceinline__ C2 ld_h2pair(const __half2* p){
    uint2 raw = *reinterpret_cast<const uint2*>(p);
    __half2 h0 = *reinterpret_cast<__half2*>(&raw.x);   // (re0, im0)
    __half2 h1 = *reinterpret_cast<__half2*>(&raw.y);   // (re1, im1)
    float2 f0 = __half22float2(h0);
    float2 f1 = __half22float2(h1);
    C2 c; c.re = pk2(f0.x, f1.x); c.im = pk2(f0.y, f1.y); return c;
}
__device__ __forceinline__ void st_h2pair(__half2* p, const C2& c){
    float r0,r1,i0,i1;
    upk2(c.re, r0, r1); upk2(c.im, i0, i1);
    __half2 h0 = __floats2half2_rn(r0, i0);
    __half2 h1 = __floats2half2_rn(r1, i1);
    uint2 raw;
    raw.x = *reinterpret_cast<u32*>(&h0);
    raw.y = *reinterpret_cast<u32*>(&h1);
    *reinterpret_cast<uint2*>(p) = raw;
}

// Factored matrix params (entries duplicated across both f32x2 lanes).
struct Mat { u64 C, SA, SAn, alr[4], ali[4], ber[4], bei[4]; };

__device__ __forceinline__ Mat load_mat(int tr){
    Mat M; const float* p = g_P[tr];
    M.C   = pk2(p[0], p[0]);
    M.SA  = pk2(p[1], p[1]);
    M.SAn = pk2(-p[1], -p[1]);
#pragma unroll
    for(int r=0;r<4;r++){
        M.alr[r] = pk2(p[2+r],  p[2+r]);
        M.ali[r] = pk2(p[6+r],  p[6+r]);
        M.ber[r] = pk2(p[10+r], p[10+r]);
        M.bei[r] = pk2(p[14+r], p[14+r]);
    }
    return M;
}

// stage DG: out_r = al_r*y_r + be_r*y_{3-r}  (full complex)
__device__ __forceinline__ void dg4(const C2* __restrict__ y, C2* __restrict__ o,
                                    const Mat& M){
    u64 ny[4];
#pragma unroll
    for(int r=0;r<4;r++) ny[r] = f2neg(y[r].im);
#pragma unroll
    for(int r=0;r<4;r++){
        int rp = 3-r;
        u64 re = f2mul(M.alr[r], y[r].re);
        re = f2fma(M.ali[r], ny[r],     re);
        re = f2fma(M.ber[r], y[rp].re,  re);
        re = f2fma(M.bei[r], ny[rp],    re);
        u64 im = f2mul(M.alr[r], y[r].im);
        im = f2fma(M.ali[r], y[r].re,   im);
        im = f2fma(M.ber[r], y[rp].im,  im);
        im = f2fma(M.bei[r], y[rp].re,  im);
        o[r].re = re; o[r].im = im;
    }
}

// stage DG, real outputs only (final digit; output is Re)
__device__ __forceinline__ void dg4_re(const C2* __restrict__ y, u64* __restrict__ o,
                                       const Mat& M){
    u64 ny[4];
#pragma unroll
    for(int r=0;r<4;r++) ny[r] = f2neg(y[r].im);
#pragma unroll
    for(int r=0;r<4;r++){
        int rp = 3-r;
        u64 re = f2mul(M.alr[r], y[r].re);
        re = f2fma(M.ali[r], ny[r],    re);
        re = f2fma(M.ber[r], y[rp].re, re);
        re = f2fma(M.bei[r], ny[rp],   re);
        o[r] = re;
    }
}

// stage A (complex input)
__device__ __forceinline__ void stA(const C2& a0, const C2& a1, const C2& a2,
                                    const C2& a3, C2* __restrict__ y, const Mat& M){
    y[0].re = f2fma(M.SAn, a2.im, f2mul(M.C, a0.re));
    y[0].im = f2fma(M.SA,  a2.re, f2mul(M.C, a0.im));
    y[2].re = f2fma(M.SAn, a0.im, f2mul(M.C, a2.re));
    y[2].im = f2fma(M.SA,  a0.re, f2mul(M.C, a2.im));
    y[1].re = f2fma(M.SAn, a3.im, f2mul(M.C, a1.re));
    y[1].im = f2fma(M.SA,  a3.re, f2mul(M.C, a1.im));
    y[3].re = f2fma(M.SAn, a1.im, f2mul(M.C, a3.re));
    y[3].im = f2fma(M.SA,  a1.re, f2mul(M.C, a3.im));
}

__device__ __forceinline__ void bfly4f(C2& a0, C2& a1, C2& a2, C2& a3, const Mat& M){
    C2 y[4], o[4];
    stA(a0,a1,a2,a3,y,M);
    dg4(y,o,M);
    a0=o[0]; a1=o[1]; a2=o[2]; a3=o[3];
}

// real-input butterfly (first digit of kJ)
__device__ __forceinline__ void bfly4fr(const u64* __restrict__ xr, C2* __restrict__ v,
                                        const Mat& M){
    C2 y[4];
    y[0].re = f2mul(M.C,  xr[0]); y[0].im = f2mul(M.SA, xr[2]);
    y[2].re = f2mul(M.C,  xr[2]); y[2].im = f2mul(M.SA, xr[0]);
    y[1].re = f2mul(M.C,  xr[1]); y[1].im = f2mul(M.SA, xr[3]);
    y[3].re = f2mul(M.C,  xr[3]); y[3].im = f2mul(M.SA, xr[1]);
    dg4(y,v,M);
}

// two digits (stride 1 then stride 4 in the 16-element register set)
__device__ __forceinline__ void digits2f(C2* __restrict__ v, const Mat& M){
#pragma unroll
    for(int g=0;g<4;g++) bfly4f(v[4*g],v[4*g+1],v[4*g+2],v[4*g+3], M);
#pragma unroll
    for(int g=0;g<4;g++) bfly4f(v[g],v[g+4],v[g+8],v[g+12], M);
}

// ---------------- K0: build factored params from weights ----------------
__global__ void k_build(const float* __restrict__ w, long long wn){
    if (threadIdx.x != 0 || blockIdx.x != 0) return;
    if (wn < 5) return;
    const float WM = 0.63245553203367586f;   // sqrt(2/5)
    float th0=w[0]*WM, th1=w[1]*WM, th2=w[2]*WM, th3=w[3]*WM, th4=w[4]*WM;
    float Cs = cosf(0.5f*(th0+th1)), Ss = sinf(0.5f*(th0+th1));
    float c2 = cosf(0.5f*th2), s2 = sinf(0.5f*th2);
    float e3 = 0.5f*th3, e4 = 0.5f*th4;
    float ddx[4], ddy[4];
    ddx[0]=cosf(e3+e4); ddy[0]=-sinf(e3+e4);
    ddx[1]=cosf(e3-e4); ddy[1]=-sinf(e3-e4);
    ddx[2]= ddx[1];     ddy[2]=-ddy[1];
    ddx[3]= ddx[0];     ddy[3]=-ddy[0];
    const float sg[4] = {1.f,-1.f,-1.f,1.f};
    g_P[0][0]=Cs; g_P[0][1]=-Ss;   // Up
    g_P[1][0]=Cs; g_P[1][1]= Ss;   // conj(Up)
    for(int r=0;r<4;r++){
        float alx = ddx[r]*c2,        aly = ddy[r]*c2;
        float bex = -sg[r]*s2*ddy[r], bey = sg[r]*s2*ddx[r];
        g_P[0][2+r]=alx;  g_P[0][6+r]=aly;  g_P[0][10+r]=bex;  g_P[0][14+r]=bey;
        g_P[1][2+r]=alx;  g_P[1][6+r]=-aly; g_P[1][10+r]=bex;  g_P[1][14+r]=-bey;
    }
}

// ---------------- kJ: ALL 6 column digits, 2 rows/CTA --------------------
// smem: XOR swizzle phys(j) = j ^ ((j>>4)&15); conflict-free all phases.
// f32x2 lanes pack rows (R0, R0+1). Output rows stored fp16.
__global__ __launch_bounds__(256,2) void kJ(const float* __restrict__ x,
                                            long long xlimf){
    extern __shared__ u64 sm[];
    u64* sre = sm;
    u64* sim = sm + 4096;
    const Mat M = load_mat(1);                 // conj(Up)
    int t = threadIdx.x;
    long long R0 = (long long)blockIdx.x * 2;
    if ((R0 + 2) * 4096LL > xlimf) return;
    const float* x0 = x + R0*NQ;
    const float* x1 = x0 + NQ;
    int tl = t & 15;
    C2 v[16];
    // phase 1: digits strides 1,4  (j = 16t + k); phys = 16t + (k ^ tl)
    {
        u64 xr[16];
        int jb = t*16;
#pragma unroll
        for(int q=0;q<4;q++){
            float4 a  = *reinterpret_cast<const float4*>(x0 + jb + 4*q);
            float4 bb = *reinterpret_cast<const float4*>(x1 + jb + 4*q);
            xr[4*q+0]=pk2(a.x,bb.x); xr[4*q+1]=pk2(a.y,bb.y);
            xr[4*q+2]=pk2(a.z,bb.z); xr[4*q+3]=pk2(a.w,bb.w);
        }
#pragma unroll
        for(int g=0;g<4;g++) bfly4fr(xr+4*g, v+4*g, M);                 // digit 0 (real in)
#pragma unroll
        for(int g=0;g<4;g++) bfly4f(v[g],v[g+4],v[g+8],v[g+12], M);     // digit 1
#pragma unroll
        for(int k=0;k<16;k++){ int p = jb + (k ^ tl); sre[p]=v[k].re; sim[p]=v[k].im; }
    }
    __syncthreads();
    // phase 2: digits strides 16,64  (j = low + 16m + 256top); phys ^= m
    {
        int base = tl + 256*(t>>4);
#pragma unroll
        for(int m=0;m<16;m++){ int p=(base+16*m)^m; v[m].re=sre[p]; v[m].im=sim[p]; }
        digits2f(v, M);
#pragma unroll
        for(int m=0;m<16;m++){ int p=(base+16*m)^m; sre[p]=v[m].re; sim[p]=v[m].im; }
    }
    __syncthreads();
    // phase 3: digits strides 256,1024  (j = t + 256m); fp16 row stores
    {
        int b3 = t ^ ((t>>4)&15);
#pragma unroll
        for(int m=0;m<16;m++){ int p=b3+256*m; v[m].re=sre[p]; v[m].im=sim[p]; }
        digits2f(v, M);
        __half2* Y0 = g_S + R0*NQ;
        __half2* Y1 = Y0 + NQ;
#pragma unroll
        for(int m=0;m<16;m++){
            int j = t + 256*m;
            float r0,r1,i0,i1;
            upk2(v[m].re,r0,r1); upk2(v[m].im,i0,i1);
            Y0[j] = __floats2half2_rn(r0, i0);
            Y1[j] = __floats2half2_rn(r1, i1);
        }
    }
}

// ---------------- kA1: row digits 0..2, 64x64 coalesced tiles ------------
__global__ __launch_bounds__(128) void kA1(){
    __half2* __restrict__ p = g_S;
    __shared__ u64 sre[2048];
    __shared__ u64 sim[2048];
    const Mat M = load_mat(0);                 // Up
    int t = threadIdx.x;
    long long base = ((long long)(blockIdx.z*4096 + blockIdx.y*64))*4096LL + blockIdx.x*64;
    int jp = t & 31;
    int g  = t >> 5;
    C2 v[16];
#pragma unroll
    for(int k=0;k<16;k++){
        long long m = 16*g + k;
        v[k] = ld_h2pair(p + base + m*4096 + 2*jp);
    }
    digits2f(v, M);
#pragma unroll
    for(int k=0;k<16;k++){ int m=16*g+k; sre[m*32+jp]=v[k].re; sim[m*32+jp]=v[k].im; }
    __syncthreads();
    int lo0 = g*4;
#pragma unroll
    for(int q=0;q<4;q++){
        int lo = lo0 + q;
        C2 wv[4];
#pragma unroll
        for(int mm=0;mm<4;mm++){ int m=lo+16*mm; wv[mm].re=sre[m*32+jp]; wv[mm].im=sim[m*32+jp]; }
        bfly4f(wv[0],wv[1],wv[2],wv[3], M);
#pragma unroll
        for(int mm=0;mm<4;mm++){
            long long m = lo + 16*mm;
            st_h2pair(p + base + m*4096 + 2*jp, wv[mm]);
        }
    }
}

// ---------------- kA2r: row digits 3..5, Re-only fp32 stores -------------
__global__ __launch_bounds__(128) void kA2r(float* __restrict__ outf,
                                            long long olimf){
    constexpr long long CS = 262144;           // 64 * 4096
    const __half2* __restrict__ p = g_S;
    __shared__ u64 sre[2048];
    __shared__ u64 sim[2048];
    const Mat M = load_mat(0);                 // Up
    int t = threadIdx.x;
    long long base = ((long long)(blockIdx.z*4096 + blockIdx.y))*4096LL + blockIdx.x*64;
    if (base + 63*CS + 64 > olimf) return;
    int jp = t & 31;
    int g  = t >> 5;
    C2 v[16];
#pragma unroll
    for(int k=0;k<16;k++){
        long long m = 16*g + k;
        v[k] = ld_h2pair(p + base + m*CS + 2*jp);
    }
    digits2f(v, M);
#pragma unroll
    for(int k=0;k<16;k++){ int m=16*g+k; sre[m*32+jp]=v[k].re; sim[m*32+jp]=v[k].im; }
    __syncthreads();
    int lo0 = g*4;
#pragma unroll
    for(int q=0;q<4;q++){
        int lo = lo0 + q;
        C2 wv[4];
#pragma unroll
        for(int mm=0;mm<4;mm++){ int m=lo+16*mm; wv[mm].re=sre[m*32+jp]; wv[mm].im=sim[m*32+jp]; }
        C2 y[4]; u64 re4[4];
        stA(wv[0],wv[1],wv[2],wv[3], y, M);
        dg4_re(y, re4, M);
#pragma unroll
        for(int mm=0;mm<4;mm++){
            long long m = lo + 16*mm;
            float r0, r1;
            upk2(re4[mm], r0, r1);
            *reinterpret_cast<float2*>(outf + base + m*CS + 2*jp) = make_float2(r0, r1);
        }
    }
}

// ---------------- launch (sequential) ------------------------------------
extern "C" void kernel_launch(void* const* d_in, const int* in_sizes, int n_in,
                              void* d_out, int out_size){
    // identify inputs: w = smallest, x = largest
    int xi = 0, wi = 0;
    for (int i = 1; i < n_in; i++){
        if (in_sizes[i] > in_sizes[xi]) xi = i;
        if (in_sizes[i] < in_sizes[wi]) wi = i;
    }
    if (xi == wi && n_in >= 2) wi = (xi == 0) ? 1 : 0;
    const float* x = (const float*)d_in[xi];
    const float* w = (const float*)d_in[wi];
    long long xlim = (long long)in_sizes[xi];
    long long wlim = (long long)in_sizes[wi];
    long long olim = (long long)out_size;

    cudaFuncSetAttribute(kJ, cudaFuncAttributeMaxDynamicSharedMemorySize, 65536);

    k_build<<<1, 32>>>(w, wlim);
    kJ<<<8192, 256, 65536>>>(x, xlim);                    // all 6 column digits
    kA1<<<dim3(64, 64, 4), 128>>>();                      // row digits 0..2
    kA2r<<<dim3(64, 64, 4), 128>>>((float*)d_out, olim);  // row digits 3..5 -> Re
}